// round 2
// baseline (speedup 1.0000x reference)
#include <cuda_runtime.h>
#include <math.h>

// Problem constants (fixed shapes)
#define BB   16
#define SS   512
#define DD   768
#define EE   128
#define RR   2048
#define HH   768
#define HH2  384
#define OUTC 2
#define ME   (BB * EE)        // 2048 entity rows
#define NREL (BB * RR)        // 32768 relations
#define RELBLOCKS (NREL / 8)  // 4096 blocks, 8 warps each

// ---------------- scratch (static device globals; no allocation) ----------------
__device__ float g_rep [ME * 2 * DD];   // [2048,1536] gathered entity reps
__device__ float g_h1h [ME * HH];       // head tower hidden
__device__ float g_h1t [ME * HH];       // tail tower hidden
__device__ float g_eH  [ME * HH2];      // head tower out
__device__ float g_eT  [ME * HH2];      // tail tower out
__device__ float g_hb  [ME * 2 * HH2];  // heads @ bil_w[o]  (o interleaved: [m][o][j])
__device__ float g_hlin[ME * 2];        // heads @ lW[:384]
__device__ float g_tlin[ME * 2];        // tails @ lW[384:]
__device__ float g_partials[RELBLOCKS]; // per-block loss partial sums

// ---------------- gather: rep[b,e] = concat(hs[b, start], emb[label]) ----------------
__global__ void gather_rep_kernel(const float* __restrict__ hs,
                                  const float* __restrict__ emb,
                                  const int* __restrict__ ent_start,
                                  const int* __restrict__ ent_label) {
    int m = blockIdx.x;                  // 0..2047
    int b = m / EE;
    int s   = ent_start[m];
    int lab = ent_label[m];
    const float4* src1 = (const float4*)(hs + ((long)b * SS + s) * DD);
    const float4* src2 = (const float4*)(emb + (long)lab * DD);
    float4* dst = (float4*)(g_rep + (long)m * 2 * DD);
    for (int i = threadIdx.x; i < DD / 4; i += blockDim.x) {
        dst[i]          = src1[i];
        dst[DD / 4 + i] = src2[i];
    }
}

// ---------------- SGEMM: C[m, n] = relu?(A[MxK] @ B[KxN] + bias) ----------------
// 64x64 tile, BK=16, 256 threads, 4x4 microtile per thread. All dims divisible.
template <bool RELU, bool HAS_BIAS>
__global__ void __launch_bounds__(256, 2)
sgemm_kernel(const float* __restrict__ A, const float* __restrict__ Bm,
             const float* __restrict__ bias, float* __restrict__ C,
             int M, int N, int K, int ldc) {
    __shared__ float As[16][64];
    __shared__ float Bs[16][64 + 4];
    const int bx = blockIdx.x;   // N tile
    const int by = blockIdx.y;   // M tile
    const int tid = threadIdx.x;
    const int tx = tid & 15;
    const int ty = tid >> 4;

    float acc[4][4] = {};
    const float* Aptr = A + (long)(by * 64) * K;
    const float* Bptr = Bm + bx * 64;

    const int ar  = tid >> 2;        // 0..63  (row within A tile)
    const int ac4 = (tid & 3) * 4;   // 0,4,8,12 (k within tile)
    const int br  = tid >> 4;        // 0..15  (k within tile)
    const int bc4 = (tid & 15) * 4;  // col within tile

    for (int k0 = 0; k0 < K; k0 += 16) {
        float4 va = *(const float4*)(Aptr + (long)ar * K + k0 + ac4);
        As[ac4 + 0][ar] = va.x;
        As[ac4 + 1][ar] = va.y;
        As[ac4 + 2][ar] = va.z;
        As[ac4 + 3][ar] = va.w;
        float4 vb = *(const float4*)(Bptr + (long)(k0 + br) * N + bc4);
        Bs[br][bc4 + 0] = vb.x;
        Bs[br][bc4 + 1] = vb.y;
        Bs[br][bc4 + 2] = vb.z;
        Bs[br][bc4 + 3] = vb.w;
        __syncthreads();
#pragma unroll
        for (int kk = 0; kk < 16; kk++) {
            float a[4], b[4];
#pragma unroll
            for (int i = 0; i < 4; i++) a[i] = As[kk][ty * 4 + i];
#pragma unroll
            for (int j = 0; j < 4; j++) b[j] = Bs[kk][tx * 4 + j];
#pragma unroll
            for (int i = 0; i < 4; i++)
#pragma unroll
                for (int j = 0; j < 4; j++) acc[i][j] = fmaf(a[i], b[j], acc[i][j]);
        }
        __syncthreads();
    }

    // epilogue (float4 stores)
    const int ncol = bx * 64 + tx * 4;
    float bsv[4] = {0.f, 0.f, 0.f, 0.f};
    if (HAS_BIAS) {
#pragma unroll
        for (int j = 0; j < 4; j++) bsv[j] = bias[ncol + j];
    }
#pragma unroll
    for (int i = 0; i < 4; i++) {
        int m = by * 64 + ty * 4 + i;
        float4 v;
        float r0 = acc[i][0] + bsv[0];
        float r1 = acc[i][1] + bsv[1];
        float r2 = acc[i][2] + bsv[2];
        float r3 = acc[i][3] + bsv[3];
        if (RELU) {
            r0 = fmaxf(r0, 0.f); r1 = fmaxf(r1, 0.f);
            r2 = fmaxf(r2, 0.f); r3 = fmaxf(r3, 0.f);
        }
        v.x = r0; v.y = r1; v.z = r2; v.w = r3;
        *(float4*)(C + (long)m * ldc + ncol) = v;
    }
}

// ---------------- per-entity linear terms: hlin/tlin[m][o] ----------------
// grid = 2048 blocks, 64 threads: warp0 -> heads (lW[0:384]), warp1 -> tails (lW[384:768])
__global__ void lin_kernel(const float* __restrict__ lW) {
    int m = blockIdx.x;
    int warp = threadIdx.x >> 5;
    int lane = threadIdx.x & 31;
    const float* src = (warp == 0) ? (g_eH + (long)m * HH2) : (g_eT + (long)m * HH2);
    int wbase = warp * HH2;
    float a0 = 0.f, a1 = 0.f;
    for (int i = lane; i < HH2; i += 32) {
        float x = src[i];
        a0 = fmaf(x, lW[(wbase + i) * 2 + 0], a0);
        a1 = fmaf(x, lW[(wbase + i) * 2 + 1], a1);
    }
#pragma unroll
    for (int off = 16; off; off >>= 1) {
        a0 += __shfl_xor_sync(0xffffffffu, a0, off);
        a1 += __shfl_xor_sync(0xffffffffu, a1, off);
    }
    if (lane == 0) {
        float* dst = (warp == 0) ? g_hlin : g_tlin;
        dst[m * 2 + 0] = a0;
        dst[m * 2 + 1] = a1;
    }
}

// ---------------- per-relation: logits + log-softmax NLL partials ----------------
// one warp per relation; 8 warps (256 thr) per block; grid = 4096
__global__ void rel_kernel(const int* __restrict__ rel_head,
                           const int* __restrict__ rel_tail,
                           const int* __restrict__ rel_label,
                           const float* __restrict__ lb,
                           float* __restrict__ out_logits) {
    int warp = threadIdx.x >> 5;
    int lane = threadIdx.x & 31;
    int r = blockIdx.x * 8 + warp;     // 0..32767 (global relation index = b*RR + rr)
    int b = r / RR;

    int hidx = rel_head[r];
    int tidx = rel_tail[r];
    long hm = (long)(b * EE + hidx);
    long tm = (long)(b * EE + tidx);
    const float* hbrow = g_hb + hm * (2 * HH2);
    const float* trow  = g_eT + tm * HH2;

    float a0 = 0.f, a1 = 0.f;
    for (int j = lane; j < HH2; j += 32) {
        float t = trow[j];
        a0 = fmaf(hbrow[j],        t, a0);
        a1 = fmaf(hbrow[HH2 + j],  t, a1);
    }
#pragma unroll
    for (int off = 16; off; off >>= 1) {
        a0 += __shfl_xor_sync(0xffffffffu, a0, off);
        a1 += __shfl_xor_sync(0xffffffffu, a1, off);
    }

    __shared__ float sloss[8];
    if (lane == 0) {
        float l0 = a0 + g_hlin[hm * 2 + 0] + g_tlin[tm * 2 + 0] + lb[0];
        float l1 = a1 + g_hlin[hm * 2 + 1] + g_tlin[tm * 2 + 1] + lb[1];
        out_logits[(long)r * 2 + 0] = l0;
        out_logits[(long)r * 2 + 1] = l1;
        float mx = fmaxf(l0, l1);
        float lse = mx + logf(expf(l0 - mx) + expf(l1 - mx));
        int lab = rel_label[r];
        sloss[warp] = (lab ? l1 : l0) - lse;
    }
    __syncthreads();
    if (threadIdx.x == 0) {
        float s = 0.f;
#pragma unroll
        for (int i = 0; i < 8; i++) s += sloss[i];
        g_partials[blockIdx.x] = s;
    }
}

// ---------------- final deterministic loss reduction ----------------
__global__ void loss_reduce_kernel(float* __restrict__ out_loss) {
    __shared__ float sh[256];
    float s = 0.f;
    for (int i = threadIdx.x; i < RELBLOCKS; i += 256) s += g_partials[i];
    sh[threadIdx.x] = s;
    __syncthreads();
    for (int off = 128; off; off >>= 1) {
        if (threadIdx.x < off) sh[threadIdx.x] += sh[threadIdx.x + off];
        __syncthreads();
    }
    if (threadIdx.x == 0) *out_loss = -sh[0] / (float)NREL;
}

// ---------------- host launch ----------------
extern "C" void kernel_launch(void* const* d_in, const int* in_sizes, int n_in,
                              void* d_out, int out_size) {
    const float* hs        = (const float*)d_in[0];   // [B,S,D]
    const float* emb       = (const float*)d_in[1];   // [3,D]
    const float* hW1       = (const float*)d_in[2];   // [1536,768]
    const float* hb1       = (const float*)d_in[3];   // [768]
    const float* hW2       = (const float*)d_in[4];   // [768,384]
    const float* hb2       = (const float*)d_in[5];   // [384]
    const float* tW1       = (const float*)d_in[6];
    const float* tb1       = (const float*)d_in[7];
    const float* tW2       = (const float*)d_in[8];
    const float* tb2       = (const float*)d_in[9];
    const float* bil_w     = (const float*)d_in[10];  // [2,384,384]
    const float* lW        = (const float*)d_in[11];  // [768,2]
    const float* lb        = (const float*)d_in[12];  // [2]
    const int*   ent_start = (const int*)d_in[13];    // [B,E]
    const int*   ent_label = (const int*)d_in[14];    // [B,E]
    const int*   rel_head  = (const int*)d_in[15];    // [B,R]
    const int*   rel_tail  = (const int*)d_in[16];    // [B,R]
    const int*   rel_label = (const int*)d_in[17];    // [B,R]

    // resolve scratch symbol addresses (host side, capture-safe: no alloc)
    float *p_rep, *p_h1h, *p_h1t, *p_eH, *p_eT, *p_hb;
    cudaGetSymbolAddress((void**)&p_rep, g_rep);
    cudaGetSymbolAddress((void**)&p_h1h, g_h1h);
    cudaGetSymbolAddress((void**)&p_h1t, g_h1t);
    cudaGetSymbolAddress((void**)&p_eH,  g_eH);
    cudaGetSymbolAddress((void**)&p_eT,  g_eT);
    cudaGetSymbolAddress((void**)&p_hb,  g_hb);

    const int logit_elems = NREL * OUTC;  // 65536
    int off = out_size - logit_elems;
    if (off < 0) off = 0;
    float* logits_out = (float*)d_out + off;

    // 1) gather entity reps
    gather_rep_kernel<<<ME, 192>>>(hs, emb, ent_start, ent_label);

    // 2) tower layer 1: [2048,1536]@[1536,768]+b, relu
    {
        dim3 grid(HH / 64, ME / 64);
        sgemm_kernel<true, true><<<grid, 256>>>(p_rep, hW1, hb1, p_h1h, ME, HH, 2 * DD, HH);
        sgemm_kernel<true, true><<<grid, 256>>>(p_rep, tW1, tb1, p_h1t, ME, HH, 2 * DD, HH);
    }
    // 3) tower layer 2: [2048,768]@[768,384]+b, relu
    {
        dim3 grid(HH2 / 64, ME / 64);
        sgemm_kernel<true, true><<<grid, 256>>>(p_h1h, hW2, hb2, p_eH, ME, HH2, HH, HH2);
        sgemm_kernel<true, true><<<grid, 256>>>(p_h1t, tW2, tb2, p_eT, ME, HH2, HH, HH2);
    }
    // 4) bilinear precompute: hb[:,o,:] = eH @ bil_w[o]   (ldc=768, col offset o*384)
    {
        dim3 grid(HH2 / 64, ME / 64);
        sgemm_kernel<false, false><<<grid, 256>>>(p_eH, bil_w,                 nullptr, p_hb,       ME, HH2, HH2, 2 * HH2);
        sgemm_kernel<false, false><<<grid, 256>>>(p_eH, bil_w + HH2 * HH2,     nullptr, p_hb + HH2, ME, HH2, HH2, 2 * HH2);
    }
    // 5) per-entity linear terms
    lin_kernel<<<ME, 64>>>(lW);

    // 6) per-relation logits + loss partials
    rel_kernel<<<RELBLOCKS, 256>>>(rel_head, rel_tail, rel_label, lb, logits_out);

    // 7) loss
    if (off >= 1) {
        loss_reduce_kernel<<<1, 256>>>((float*)d_out);
    }
}

// round 6
// speedup vs baseline: 1.8200x; 1.8200x over previous
#include <cuda_runtime.h>
#include <cuda_bf16.h>
#include <stdint.h>
#include <math.h>

// ---------------- problem constants ----------------
#define BB   16
#define SS_  512
#define DD   768
#define EE   128
#define RR   2048
#define HH   768
#define HH2  384
#define ME   (BB * EE)        // 2048 entity rows
#define NREL (BB * RR)        // 32768 relations
#define RELBLOCKS (NREL / 8)
#define K1   (2 * DD)         // 1536
#define N1   (2 * HH)         // 1536 (head|tail fused)

// ---------------- scratch (static device globals) ----------------
__device__ __nv_bfloat16 g_repH[ME * K1],  g_repL[ME * K1];
__device__ __nv_bfloat16 g_w1H [N1 * K1],  g_w1L [N1 * K1];        // [N,K]
__device__ __nv_bfloat16 g_h1H [ME * N1],  g_h1L [ME * N1];
__device__ __nv_bfloat16 g_w2hH[HH2 * HH], g_w2hL[HH2 * HH];
__device__ __nv_bfloat16 g_w2tH[HH2 * HH], g_w2tL[HH2 * HH];
__device__ __nv_bfloat16 g_eHH [ME * HH2], g_eHL [ME * HH2];
__device__ __nv_bfloat16 g_bilH[2 * HH2 * HH2], g_bilL[2 * HH2 * HH2];
__device__ float g_eH[ME * HH2], g_eT[ME * HH2];
__device__ float g_hb[ME * 2 * HH2];
__device__ float g_hlin[ME * 2], g_tlin[ME * 2];
__device__ float g_partials[RELBLOCKS];

// ---------------- helpers ----------------
__device__ __forceinline__ uint32_t smem_u32(const void* p) {
    uint32_t a;
    asm("{ .reg .u64 t; cvta.to.shared.u64 t, %1; cvt.u32.u64 %0, t; }" : "=r"(a) : "l"(p));
    return a;
}
__device__ __forceinline__ void cpa16(uint32_t dst, const void* src) {
    asm volatile("cp.async.cg.shared.global [%0], [%1], 16;" :: "r"(dst), "l"(src));
}
#define CP_COMMIT() asm volatile("cp.async.commit_group;" ::: "memory")

#define LDSM4(r, addr) \
    asm volatile("ldmatrix.sync.aligned.m8n8.x4.shared.b16 {%0,%1,%2,%3}, [%4];" \
        : "=r"((r)[0]), "=r"((r)[1]), "=r"((r)[2]), "=r"((r)[3]) : "r"(addr))

#define MMA16816(d, a, b) \
    asm volatile("mma.sync.aligned.m16n8k16.row.col.f32.bf16.bf16.f32 " \
        "{%0,%1,%2,%3}, {%4,%5,%6,%7}, {%8,%9}, {%0,%1,%2,%3};" \
        : "+f"((d)[0]), "+f"((d)[1]), "+f"((d)[2]), "+f"((d)[3]) \
        : "r"((a)[0]), "r"((a)[1]), "r"((a)[2]), "r"((a)[3]), "r"((b)[0]), "r"((b)[1]))

__device__ __forceinline__ void split2(float x, __nv_bfloat16& h, __nv_bfloat16& l) {
    h = __float2bfloat16(x);
    l = __float2bfloat16(x - __bfloat162float(h));
}

// ---------------- gather + convert ----------------
__global__ void gather_kernel(const float* __restrict__ hs, const float* __restrict__ emb,
                              const int* __restrict__ es, const int* __restrict__ el) {
    int m = blockIdx.x;
    int b = m >> 7;
    int s = es[m], lab = el[m];
    const float* src1 = hs + ((size_t)b * SS_ + s) * DD;
    const float* src2 = emb + (size_t)lab * DD;
    size_t rb = (size_t)m * K1;
    for (int i = threadIdx.x; i < DD; i += 256) {
        __nv_bfloat16 h, l;
        split2(src1[i], h, l);
        g_repH[rb + i] = h; g_repL[rb + i] = l;
        split2(src2[i], h, l);
        g_repH[rb + DD + i] = h; g_repL[rb + DD + i] = l;
    }
}

// ---------------- weight transpose+convert: W[K,N] -> [N,K] hi/lo ----------------
__global__ void wconv_kernel(const float* __restrict__ W, int K, int N,
                             __nv_bfloat16* __restrict__ outH, __nv_bfloat16* __restrict__ outL) {
    __shared__ float t[32][33];
    int n0 = blockIdx.x * 32, k0 = blockIdx.y * 32;
    int tx = threadIdx.x, ty = threadIdx.y;
#pragma unroll
    for (int j = 0; j < 32; j += 8)
        t[ty + j][tx] = W[(size_t)(k0 + ty + j) * N + n0 + tx];
    __syncthreads();
#pragma unroll
    for (int j = 0; j < 32; j += 8) {
        int n = n0 + ty + j, k = k0 + tx;
        __nv_bfloat16 h, l;
        split2(t[tx][ty + j], h, l);
        outH[(size_t)n * K + k] = h;
        outL[(size_t)n * K + k] = l;
    }
}

// ---------------- mma.sync split-bf16 GEMM ----------------
// C[128x128 tile] = A[M,K] (row-major) @ B[N,K]^T, 3 split terms into fp32 accum.
// SMEM per stage: Ahi(128x80B)=10240 | Alo 10240 | Bhi 10240 | Blo 10240 = 40960; x2 stages.
#define ROWB   80
#define MATB   10240
#define STAGEB 40960
#define GEMM_SMEM (2 * STAGEB)

__device__ __forceinline__ void load_stage(uint32_t sbase,
        const __nv_bfloat16* __restrict__ aH, const __nv_bfloat16* __restrict__ aL,
        int lda, int m0,
        const __nv_bfloat16* __restrict__ bH, const __nv_bfloat16* __restrict__ bL,
        int ldb, int n0, int k0, int tid) {
#pragma unroll
    for (int i = 0; i < 2; i++) {
        int idx = i * 256 + tid;
        int row = idx >> 2, ch = idx & 3;
        uint32_t d = sbase + row * ROWB + ch * 16;
        cpa16(d,            aH + (size_t)(m0 + row) * lda + k0 + ch * 8);
        cpa16(d + MATB,     aL + (size_t)(m0 + row) * lda + k0 + ch * 8);
        cpa16(d + 2 * MATB, bH + (size_t)(n0 + row) * ldb + k0 + ch * 8);
        cpa16(d + 3 * MATB, bL + (size_t)(n0 + row) * ldb + k0 + ch * 8);
    }
}

template <bool RELU, bool HAS_BIAS, bool OUT_BF16, bool OUT_F32>
__global__ void __launch_bounds__(256)
mma_gemm(const __nv_bfloat16* __restrict__ aH, const __nv_bfloat16* __restrict__ aL, int lda,
         const __nv_bfloat16* __restrict__ bH, const __nv_bfloat16* __restrict__ bL,
         const float* __restrict__ bias0, const float* __restrict__ bias1, int biasSplit,
         __nv_bfloat16* __restrict__ outH, __nv_bfloat16* __restrict__ outL,
         float* __restrict__ outF, int ldo, int K) {
    extern __shared__ char smem[];
    const uint32_t sb = smem_u32(smem);
    const int tid = threadIdx.x;
    const int wid = tid >> 5, lane = tid & 31;
    const int m0 = blockIdx.y * 128, n0 = blockIdx.x * 128;
    const int warpM = (wid >> 2) * 64;   // 0 or 64
    const int warpN = (wid & 3) * 32;    // 0,32,64,96

    // ldmatrix per-lane offsets (within a matrix region, before mt/np/ks adds)
    const uint32_t aOff = (warpM + (lane & 15)) * ROWB + (lane >> 4) * 16;
    const uint32_t bOff = (warpN + (lane & 7) + ((lane >> 4) & 1) * 8) * ROWB
                        + ((lane >> 3) & 1) * 16;

    float acc[4][4][4];
#pragma unroll
    for (int i = 0; i < 4; i++)
#pragma unroll
        for (int j = 0; j < 4; j++)
#pragma unroll
            for (int q = 0; q < 4; q++) acc[i][j][q] = 0.f;

    const int NC = K >> 5;
    load_stage(sb, aH, aL, lda, m0, bH, bL, K, n0, 0, tid);
    CP_COMMIT();

    for (int c = 0; c < NC; c++) {
        if (c + 1 < NC) {
            load_stage(sb + ((c + 1) & 1) * STAGEB, aH, aL, lda, m0, bH, bL, K, n0,
                       (c + 1) * 32, tid);
            CP_COMMIT();
            asm volatile("cp.async.wait_group 1;" ::: "memory");
        } else {
            asm volatile("cp.async.wait_group 0;" ::: "memory");
        }
        __syncthreads();

        const uint32_t st = sb + (c & 1) * STAGEB;
#pragma unroll
        for (int ks = 0; ks < 2; ks++) {
            uint32_t ah[4][4], al[4][4], bh[2][4], bl[2][4];
#pragma unroll
            for (int mt = 0; mt < 4; mt++) {
                uint32_t ad = st + aOff + mt * (16 * ROWB) + ks * 32;
                LDSM4(ah[mt], ad);
                LDSM4(al[mt], ad + MATB);
            }
#pragma unroll
            for (int np = 0; np < 2; np++) {
                uint32_t bd = st + 2 * MATB + bOff + np * (16 * ROWB) + ks * 32;
                LDSM4(bh[np], bd);
                LDSM4(bl[np], bd + MATB);
            }
#pragma unroll
            for (int mt = 0; mt < 4; mt++)
#pragma unroll
                for (int nt = 0; nt < 4; nt++) {
                    uint32_t* bhp = &bh[nt >> 1][(nt & 1) * 2];
                    uint32_t* blp = &bl[nt >> 1][(nt & 1) * 2];
                    MMA16816(acc[mt][nt], ah[mt], bhp);
                    MMA16816(acc[mt][nt], ah[mt], blp);
                    MMA16816(acc[mt][nt], al[mt], bhp);
                }
        }
        __syncthreads();
    }

    // ---------------- epilogue ----------------
    const int lr = lane >> 2;          // 0..7
    const int lc = (lane & 3) * 2;
    const float* bbase = nullptr;
    int bshift = 0;
    if (HAS_BIAS) {
        // per-CTA-column-range bias pointer (biasSplit is a multiple of 128 here)
        bbase = (biasSplit && n0 >= biasSplit) ? bias1 : bias0;
        bshift = (biasSplit && n0 >= biasSplit) ? (n0 - biasSplit) : n0;
        bshift -= n0;  // so index = gcol - n0 + ... ; net: bbase[gcol + bshift]
    }
#pragma unroll
    for (int mt = 0; mt < 4; mt++) {
#pragma unroll
        for (int nt = 0; nt < 4; nt++) {
            int grow = m0 + warpM + mt * 16 + lr;
            int gcol = n0 + warpN + nt * 8 + lc;
            float v0 = acc[mt][nt][0], v1 = acc[mt][nt][1];
            float v2 = acc[mt][nt][2], v3 = acc[mt][nt][3];
            if (HAS_BIAS) {
                float b0v = __ldg(bbase + gcol + bshift), b1v = __ldg(bbase + gcol + bshift + 1);
                v0 += b0v; v1 += b1v; v2 += b0v; v3 += b1v;
            }
            if (RELU) {
                v0 = fmaxf(v0, 0.f); v1 = fmaxf(v1, 0.f);
                v2 = fmaxf(v2, 0.f); v3 = fmaxf(v3, 0.f);
            }
            if (OUT_F32) {
                *(float2*)(outF + (size_t)grow * ldo + gcol)       = make_float2(v0, v1);
                *(float2*)(outF + (size_t)(grow + 8) * ldo + gcol) = make_float2(v2, v3);
            }
            if (OUT_BF16) {
                __nv_bfloat16 h0, l0, h1, l1, h2, l2, h3, l3;
                split2(v0, h0, l0); split2(v1, h1, l1);
                split2(v2, h2, l2); split2(v3, h3, l3);
                *(__nv_bfloat162*)(outH + (size_t)grow * ldo + gcol)       = __nv_bfloat162(h0, h1);
                *(__nv_bfloat162*)(outL + (size_t)grow * ldo + gcol)       = __nv_bfloat162(l0, l1);
                *(__nv_bfloat162*)(outH + (size_t)(grow + 8) * ldo + gcol) = __nv_bfloat162(h2, h3);
                *(__nv_bfloat162*)(outL + (size_t)(grow + 8) * ldo + gcol) = __nv_bfloat162(l2, l3);
            }
        }
    }
}

// ---------------- per-entity linear terms ----------------
__global__ void lin_kernel(const float* __restrict__ lW) {
    int m = blockIdx.x;
    int warp = threadIdx.x >> 5;
    int lane = threadIdx.x & 31;
    const float* src = (warp == 0) ? (g_eH + (size_t)m * HH2) : (g_eT + (size_t)m * HH2);
    int wbase = warp * HH2;
    float a0 = 0.f, a1 = 0.f;
    for (int i = lane; i < HH2; i += 32) {
        float x = src[i];
        a0 = fmaf(x, lW[(wbase + i) * 2 + 0], a0);
        a1 = fmaf(x, lW[(wbase + i) * 2 + 1], a1);
    }
#pragma unroll
    for (int off = 16; off; off >>= 1) {
        a0 += __shfl_xor_sync(0xffffffffu, a0, off);
        a1 += __shfl_xor_sync(0xffffffffu, a1, off);
    }
    if (lane == 0) {
        float* dst = (warp == 0) ? g_hlin : g_tlin;
        dst[m * 2 + 0] = a0;
        dst[m * 2 + 1] = a1;
    }
}

// ---------------- per-relation logits + NLL partials ----------------
__global__ void rel_kernel(const int* __restrict__ rel_head, const int* __restrict__ rel_tail,
                           const int* __restrict__ rel_label, const float* __restrict__ lb,
                           float* __restrict__ out_logits) {
    int warp = threadIdx.x >> 5;
    int lane = threadIdx.x & 31;
    int r = blockIdx.x * 8 + warp;
    int b = r / RR;
    int hidx = rel_head[r];
    int tidx = rel_tail[r];
    size_t hm = (size_t)(b * EE + hidx);
    size_t tm = (size_t)(b * EE + tidx);
    const float* hbrow = g_hb + hm * (2 * HH2);
    const float* trow  = g_eT + tm * HH2;
    float a0 = 0.f, a1 = 0.f;
    for (int j = lane; j < HH2; j += 32) {
        float t = trow[j];
        a0 = fmaf(hbrow[j],       t, a0);
        a1 = fmaf(hbrow[HH2 + j], t, a1);
    }
#pragma unroll
    for (int off = 16; off; off >>= 1) {
        a0 += __shfl_xor_sync(0xffffffffu, a0, off);
        a1 += __shfl_xor_sync(0xffffffffu, a1, off);
    }
    __shared__ float sloss[8];
    if (lane == 0) {
        float l0 = a0 + g_hlin[hm * 2 + 0] + g_tlin[tm * 2 + 0] + lb[0];
        float l1 = a1 + g_hlin[hm * 2 + 1] + g_tlin[tm * 2 + 1] + lb[1];
        out_logits[(size_t)r * 2 + 0] = l0;
        out_logits[(size_t)r * 2 + 1] = l1;
        float mx = fmaxf(l0, l1);
        float lse = mx + logf(expf(l0 - mx) + expf(l1 - mx));
        int lab = rel_label[r];
        sloss[warp] = (lab ? l1 : l0) - lse;
    }
    __syncthreads();
    if (threadIdx.x == 0) {
        float s = 0.f;
#pragma unroll
        for (int i = 0; i < 8; i++) s += sloss[i];
        g_partials[blockIdx.x] = s;
    }
}

__global__ void loss_reduce_kernel(float* __restrict__ out_loss) {
    __shared__ float sh[256];
    float s = 0.f;
    for (int i = threadIdx.x; i < RELBLOCKS; i += 256) s += g_partials[i];
    sh[threadIdx.x] = s;
    __syncthreads();
    for (int off = 128; off; off >>= 1) {
        if (threadIdx.x < off) sh[threadIdx.x] += sh[threadIdx.x + off];
        __syncthreads();
    }
    if (threadIdx.x == 0) *out_loss = -sh[0] / (float)NREL;
}

// ---------------- host launch ----------------
extern "C" void kernel_launch(void* const* d_in, const int* in_sizes, int n_in,
                              void* d_out, int out_size) {
    const float* hs        = (const float*)d_in[0];
    const float* emb       = (const float*)d_in[1];
    const float* hW1       = (const float*)d_in[2];
    const float* hb1       = (const float*)d_in[3];
    const float* hW2       = (const float*)d_in[4];
    const float* hb2       = (const float*)d_in[5];
    const float* tW1       = (const float*)d_in[6];
    const float* tb1       = (const float*)d_in[7];
    const float* tW2       = (const float*)d_in[8];
    const float* tb2       = (const float*)d_in[9];
    const float* bil_w     = (const float*)d_in[10];
    const float* lW        = (const float*)d_in[11];
    const float* lb        = (const float*)d_in[12];
    const int*   ent_start = (const int*)d_in[13];
    const int*   ent_label = (const int*)d_in[14];
    const int*   rel_head  = (const int*)d_in[15];
    const int*   rel_tail  = (const int*)d_in[16];
    const int*   rel_label = (const int*)d_in[17];

    cudaFuncSetAttribute(mma_gemm<true,  true,  true,  false>, cudaFuncAttributeMaxDynamicSharedMemorySize, GEMM_SMEM);
    cudaFuncSetAttribute(mma_gemm<true,  true,  true,  true >, cudaFuncAttributeMaxDynamicSharedMemorySize, GEMM_SMEM);
    cudaFuncSetAttribute(mma_gemm<true,  true,  false, true >, cudaFuncAttributeMaxDynamicSharedMemorySize, GEMM_SMEM);
    cudaFuncSetAttribute(mma_gemm<false, false, false, true >, cudaFuncAttributeMaxDynamicSharedMemorySize, GEMM_SMEM);

    __nv_bfloat16 *p_repH, *p_repL, *p_w1H, *p_w1L, *p_h1H, *p_h1L;
    __nv_bfloat16 *p_w2hH, *p_w2hL, *p_w2tH, *p_w2tL, *p_eHH, *p_eHL, *p_bilH, *p_bilL;
    float *p_eH, *p_eT, *p_hb;
    cudaGetSymbolAddress((void**)&p_repH, g_repH); cudaGetSymbolAddress((void**)&p_repL, g_repL);
    cudaGetSymbolAddress((void**)&p_w1H,  g_w1H ); cudaGetSymbolAddress((void**)&p_w1L,  g_w1L );
    cudaGetSymbolAddress((void**)&p_h1H,  g_h1H ); cudaGetSymbolAddress((void**)&p_h1L,  g_h1L );
    cudaGetSymbolAddress((void**)&p_w2hH, g_w2hH); cudaGetSymbolAddress((void**)&p_w2hL, g_w2hL);
    cudaGetSymbolAddress((void**)&p_w2tH, g_w2tH); cudaGetSymbolAddress((void**)&p_w2tL, g_w2tL);
    cudaGetSymbolAddress((void**)&p_eHH,  g_eHH ); cudaGetSymbolAddress((void**)&p_eHL,  g_eHL );
    cudaGetSymbolAddress((void**)&p_bilH, g_bilH); cudaGetSymbolAddress((void**)&p_bilL, g_bilL);
    cudaGetSymbolAddress((void**)&p_eH,   g_eH  ); cudaGetSymbolAddress((void**)&p_eT,   g_eT  );
    cudaGetSymbolAddress((void**)&p_hb,   g_hb  );

    const int logit_elems = NREL * 2;
    int off = out_size - logit_elems;
    if (off < 0) off = 0;
    float* logits_out = (float*)d_out + off;

    // 1) gather + convert A (layer 1)
    gather_kernel<<<ME, 256>>>(hs, emb, ent_start, ent_label);

    // 2) weight transpose+convert to [N,K] bf16 hi/lo
    {
        dim3 blk(32, 8);
        wconv_kernel<<<dim3(HH  / 32, K1  / 32), blk>>>(hW1, K1, HH, p_w1H, p_w1L);
        wconv_kernel<<<dim3(HH  / 32, K1  / 32), blk>>>(tW1, K1, HH,
                       p_w1H + (size_t)HH * K1, p_w1L + (size_t)HH * K1);
        wconv_kernel<<<dim3(HH2 / 32, HH  / 32), blk>>>(hW2, HH, HH2, p_w2hH, p_w2hL);
        wconv_kernel<<<dim3(HH2 / 32, HH  / 32), blk>>>(tW2, HH, HH2, p_w2tH, p_w2tL);
        wconv_kernel<<<dim3(HH2 / 32, HH2 / 32), blk>>>(bil_w,             HH2, HH2, p_bilH,             p_bilL);
        wconv_kernel<<<dim3(HH2 / 32, HH2 / 32), blk>>>(bil_w + HH2 * HH2, HH2, HH2,
                       p_bilH + HH2 * HH2, p_bilL + HH2 * HH2);
    }

    // 3) layer 1 (fused head|tail): [2048,1536] x [1536,1536]^T, relu, bf16 out
    mma_gemm<true, true, true, false><<<dim3(N1 / 128, ME / 128), 256, GEMM_SMEM>>>(
        p_repH, p_repL, K1, p_w1H, p_w1L, hb1, tb1, HH,
        p_h1H, p_h1L, nullptr, N1, K1);

    // 4) layer 2 head: bf16 + fp32 out; tail: fp32 out only
    mma_gemm<true, true, true, true><<<dim3(HH2 / 128, ME / 128), 256, GEMM_SMEM>>>(
        p_h1H, p_h1L, N1, p_w2hH, p_w2hL, hb2, nullptr, 0,
        p_eHH, p_eHL, p_eH, HH2, HH);
    mma_gemm<true, true, false, true><<<dim3(HH2 / 128, ME / 128), 256, GEMM_SMEM>>>(
        p_h1H + HH, p_h1L + HH, N1, p_w2tH, p_w2tL, tb2, nullptr, 0,
        nullptr, nullptr, p_eT, HH2, HH);

    // 5) bilinear precompute: hb[m, o*384+j] = sum_i eH[m,i] * bil_w[o,i,j]
    mma_gemm<false, false, false, true><<<dim3(2 * HH2 / 128, ME / 128), 256, GEMM_SMEM>>>(
        p_eHH, p_eHL, HH2, p_bilH, p_bilL, nullptr, nullptr, 0,
        nullptr, nullptr, p_hb, 2 * HH2, HH2);

    // 6) per-entity linear terms
    lin_kernel<<<ME, 64>>>(lW);

    // 7) per-relation logits + loss partials
    rel_kernel<<<RELBLOCKS, 256>>>(rel_head, rel_tail, rel_label, lb, logits_out);

    // 8) loss
    if (off >= 1) loss_reduce_kernel<<<1, 256>>>((float*)d_out);
}

// round 7
// speedup vs baseline: 2.6795x; 1.4723x over previous
#include <cuda_runtime.h>
#include <cuda_bf16.h>
#include <stdint.h>
#include <math.h>

// ---------------- problem constants ----------------
#define BB   16
#define SS_  512
#define DD   768
#define EE   128
#define RR   2048
#define HH   768
#define HH2  384
#define ME   (BB * EE)        // 2048 entity rows
#define NREL (BB * RR)        // 32768 relations
#define RELBLOCKS (NREL / 8)
#define N1   (2 * HH)         // 1536 (head|tail fused layer1 output)

// ---------------- scratch (static device globals) ----------------
__device__ __nv_bfloat16 g_repH[ME * DD],  g_repL[ME * DD];        // hid part only, [2048,768]
__device__ __nv_bfloat16 g_w1H [N1 * DD],  g_w1L [N1 * DD];        // W1 top halves, [1536,768] (N,K)
__device__ __nv_bfloat16 g_h1H [ME * N1],  g_h1L [ME * N1];
__device__ __nv_bfloat16 g_w2hH[HH2 * HH], g_w2hL[HH2 * HH];
__device__ __nv_bfloat16 g_w2tH[HH2 * HH], g_w2tL[HH2 * HH];
__device__ __nv_bfloat16 g_eHH [ME * HH2], g_eHL [ME * HH2];
__device__ __nv_bfloat16 g_bilH[2 * HH2 * HH2], g_bilL[2 * HH2 * HH2];
__device__ float g_embW1[3 * N1];            // emb@W1_bot + b1 (head|tail), exact fp32
__device__ float g_eH[ME * HH2], g_eT[ME * HH2];
__device__ float g_hb[ME * 2 * HH2];
__device__ float g_hlin[ME * 2], g_tlin[ME * 2];
__device__ float g_partials[RELBLOCKS];

// ---------------- helpers ----------------
__device__ __forceinline__ uint32_t smem_u32(const void* p) {
    uint32_t a;
    asm("{ .reg .u64 t; cvta.to.shared.u64 t, %1; cvt.u32.u64 %0, t; }" : "=r"(a) : "l"(p));
    return a;
}
__device__ __forceinline__ void cpa16(uint32_t dst, const void* src) {
    asm volatile("cp.async.cg.shared.global [%0], [%1], 16;" :: "r"(dst), "l"(src));
}
#define CP_COMMIT() asm volatile("cp.async.commit_group;" ::: "memory")

#define LDSM4(r, addr) \
    asm volatile("ldmatrix.sync.aligned.m8n8.x4.shared.b16 {%0,%1,%2,%3}, [%4];" \
        : "=r"((r)[0]), "=r"((r)[1]), "=r"((r)[2]), "=r"((r)[3]) : "r"(addr))

#define MMA16816(d, a, b) \
    asm volatile("mma.sync.aligned.m16n8k16.row.col.f32.bf16.bf16.f32 " \
        "{%0,%1,%2,%3}, {%4,%5,%6,%7}, {%8,%9}, {%0,%1,%2,%3};" \
        : "+f"((d)[0]), "+f"((d)[1]), "+f"((d)[2]), "+f"((d)[3]) \
        : "r"((a)[0]), "r"((a)[1]), "r"((a)[2]), "r"((a)[3]), "r"((b)[0]), "r"((b)[1]))

__device__ __forceinline__ void split2(float x, __nv_bfloat16& h, __nv_bfloat16& l) {
    h = __float2bfloat16(x);
    l = __float2bfloat16(x - __bfloat162float(h));
}

// ---------------- gather + convert (hid part only) ----------------
__global__ void gather_kernel(const float* __restrict__ hs,
                              const int* __restrict__ es) {
    int m = blockIdx.x;
    int b = m >> 7;
    int s = es[m];
    const float* src = hs + ((size_t)b * SS_ + s) * DD;
    size_t rb = (size_t)m * DD;
    for (int i = threadIdx.x; i < DD; i += 256) {
        __nv_bfloat16 h, l;
        split2(src[i], h, l);
        g_repH[rb + i] = h; g_repL[rb + i] = l;
    }
}

// ---------------- embW1[l, n] = emb[l] @ W1_bottom[:, n] + b1[n]  (exact fp32) ----------------
// 3*1536 = 4608 outputs; one warp each; 576 blocks x 256 threads
__global__ void embw1_kernel(const float* __restrict__ emb,
                             const float* __restrict__ hW1, const float* __restrict__ hb1,
                             const float* __restrict__ tW1, const float* __restrict__ tb1) {
    int o = blockIdx.x * 8 + (threadIdx.x >> 5);
    int lane = threadIdx.x & 31;
    int l = o / N1, n = o % N1;
    const float* er = emb + (size_t)l * DD;
    const float* w;
    float bias;
    if (n < HH) { w = hW1 + (size_t)DD * HH + n;        bias = hb1[n]; }
    else        { w = tW1 + (size_t)DD * HH + (n - HH); bias = tb1[n - HH]; }
    float a = 0.f;
    for (int k = lane; k < DD; k += 32) a = fmaf(er[k], w[(size_t)k * HH], a);
#pragma unroll
    for (int off = 16; off; off >>= 1) a += __shfl_xor_sync(0xffffffffu, a, off);
    if (lane == 0) g_embW1[o] = a + bias;
}

// ---------------- all weight transposes+converts in ONE launch ----------------
// jobs (block ranges): hW1top 576 | tW1top 576 | hW2 288 | tW2 288 | bil0 144 | bil1 144
__global__ void wconv_all(const float* __restrict__ hW1, const float* __restrict__ tW1,
                          const float* __restrict__ hW2, const float* __restrict__ tW2,
                          const float* __restrict__ bil) {
    __shared__ float t[32][33];
    int id = blockIdx.x;
    const float* W; int K, N; __nv_bfloat16 *oH, *oL;
    if (id < 576)       { W = hW1;             K = 768; N = 768; oH = g_w1H;             oL = g_w1L; }
    else if (id < 1152) { W = tW1;             K = 768; N = 768; oH = g_w1H + 768 * 768; oL = g_w1L + 768 * 768; id -= 576; }
    else if (id < 1440) { W = hW2;             K = 768; N = 384; oH = g_w2hH;            oL = g_w2hL; id -= 1152; }
    else if (id < 1728) { W = tW2;             K = 768; N = 384; oH = g_w2tH;            oL = g_w2tL; id -= 1440; }
    else if (id < 1872) { W = bil;             K = 384; N = 384; oH = g_bilH;            oL = g_bilL; id -= 1728; }
    else                { W = bil + 384 * 384; K = 384; N = 384; oH = g_bilH + 384 * 384; oL = g_bilL + 384 * 384; id -= 1872; }
    int ntiles = N / 32;
    int n0 = (id % ntiles) * 32, k0 = (id / ntiles) * 32;
    int tx = threadIdx.x, ty = threadIdx.y;
#pragma unroll
    for (int j = 0; j < 32; j += 8)
        t[ty + j][tx] = W[(size_t)(k0 + ty + j) * N + n0 + tx];
    __syncthreads();
#pragma unroll
    for (int j = 0; j < 32; j += 8) {
        int n = n0 + ty + j, k = k0 + tx;
        __nv_bfloat16 h, l;
        split2(t[tx][ty + j], h, l);
        oH[(size_t)n * K + k] = h;
        oL[(size_t)n * K + k] = l;
    }
}

// ---------------- mma.sync split-bf16 GEMM (templated tile M, 2-job batched) ----------------
// C[BMxBN=128] tile = A[M,K] @ B[N,K]^T ; 3 split terms into fp32 accum.
// SMEM stage: Ahi(BM*80) Alo Bhi(128*80) Blo ; 2 stages.
struct GJob {
    const __nv_bfloat16 *aH, *aL; int lda;
    const __nv_bfloat16 *bH, *bL;            // ldb = K
    const float* bias;                       // per-local-col or null
    const float* rowTab; const int* rowLab; int ldTab;   // per-row table or null
    __nv_bfloat16 *outH, *outL;              // bf16 hi/lo out or null
    float* outF;                             // fp32 out or null
    int ldo;
    int relu;
};

template <int BM>
__device__ __forceinline__ void load_stage(uint32_t sbase, const GJob& j,
                                           int m0, int n0, int k0, int tid, int K) {
    const int ACH = BM * 4;                  // 16B chunks per A matrix
#pragma unroll
    for (int idx = tid; idx < 2 * ACH + 1024; idx += 256) {
        if (idx < ACH) {
            int row = idx >> 2, ch = idx & 3;
            cpa16(sbase + row * 80 + ch * 16, j.aH + (size_t)(m0 + row) * j.lda + k0 + ch * 8);
        } else if (idx < 2 * ACH) {
            int q = idx - ACH; int row = q >> 2, ch = q & 3;
            cpa16(sbase + BM * 80 + row * 80 + ch * 16, j.aL + (size_t)(m0 + row) * j.lda + k0 + ch * 8);
        } else if (idx < 2 * ACH + 512) {
            int q = idx - 2 * ACH; int row = q >> 2, ch = q & 3;
            cpa16(sbase + 2 * BM * 80 + row * 80 + ch * 16, j.bH + (size_t)(n0 + row) * K + k0 + ch * 8);
        } else {
            int q = idx - 2 * ACH - 512; int row = q >> 2, ch = q & 3;
            cpa16(sbase + 2 * BM * 80 + 10240 + row * 80 + ch * 16, j.bL + (size_t)(n0 + row) * K + k0 + ch * 8);
        }
    }
}

template <int BM>
__global__ void __launch_bounds__(256)
mma_gemm(GJob j0, GJob j1, int splitX, int K) {
    constexpr int MT = BM / 32;              // m16 tiles per warp (4 or 2)
    constexpr int MAT_A = BM * 80;
    constexpr int OFF_B = 2 * BM * 80;
    constexpr int STAGE = 2 * BM * 80 + 20480;
    extern __shared__ char smem[];
    const uint32_t sb = smem_u32(smem);
    const int tid = threadIdx.x;
    const int wid = tid >> 5, lane = tid & 31;

    const int isJ1 = (blockIdx.x >= splitX);
    const GJob j = isJ1 ? j1 : j0;
    const int nx = blockIdx.x - (isJ1 ? splitX : 0);
    const int m0 = blockIdx.y * BM, n0 = nx * 128;
    const int warpM = (wid >> 2) * (BM / 2);
    const int warpN = (wid & 3) * 32;

    const uint32_t aOff = (warpM + (lane & 15)) * 80 + (lane >> 4) * 16;
    const uint32_t bOff = (warpN + (lane & 7) + ((lane >> 4) & 1) * 8) * 80
                        + ((lane >> 3) & 1) * 16;

    float acc[MT][4][4];
#pragma unroll
    for (int i = 0; i < MT; i++)
#pragma unroll
        for (int jt = 0; jt < 4; jt++)
#pragma unroll
            for (int q = 0; q < 4; q++) acc[i][jt][q] = 0.f;

    const int NC = K >> 5;
    load_stage<BM>(sb, j, m0, n0, 0, tid, K);
    CP_COMMIT();

    for (int c = 0; c < NC; c++) {
        if (c + 1 < NC) {
            load_stage<BM>(sb + ((c + 1) & 1) * STAGE, j, m0, n0, (c + 1) * 32, tid, K);
            CP_COMMIT();
            asm volatile("cp.async.wait_group 1;" ::: "memory");
        } else {
            asm volatile("cp.async.wait_group 0;" ::: "memory");
        }
        __syncthreads();

        const uint32_t st = sb + (c & 1) * STAGE;
#pragma unroll
        for (int ks = 0; ks < 2; ks++) {
            uint32_t ah[MT][4], al[MT][4], bh[2][4], bl[2][4];
#pragma unroll
            for (int mt = 0; mt < MT; mt++) {
                uint32_t ad = st + aOff + mt * (16 * 80) + ks * 32;
                LDSM4(ah[mt], ad);
                LDSM4(al[mt], ad + MAT_A);
            }
#pragma unroll
            for (int np = 0; np < 2; np++) {
                uint32_t bd = st + OFF_B + bOff + np * (16 * 80) + ks * 32;
                LDSM4(bh[np], bd);
                LDSM4(bl[np], bd + 10240);
            }
#pragma unroll
            for (int mt = 0; mt < MT; mt++)
#pragma unroll
                for (int nt = 0; nt < 4; nt++) {
                    uint32_t* bhp = &bh[nt >> 1][(nt & 1) * 2];
                    uint32_t* blp = &bl[nt >> 1][(nt & 1) * 2];
                    MMA16816(acc[mt][nt], ah[mt], bhp);
                    MMA16816(acc[mt][nt], ah[mt], blp);
                    MMA16816(acc[mt][nt], al[mt], bhp);
                }
        }
        __syncthreads();
    }

    // ---------------- epilogue (runtime-flagged) ----------------
    const int lr = lane >> 2;
    const int lc = (lane & 3) * 2;
#pragma unroll
    for (int mt = 0; mt < MT; mt++) {
        int grow = m0 + warpM + mt * 16 + lr;
        int lab0 = 0, lab1 = 0;
        if (j.rowTab) { lab0 = j.rowLab[grow]; lab1 = j.rowLab[grow + 8]; }
#pragma unroll
        for (int nt = 0; nt < 4; nt++) {
            int gcol = n0 + warpN + nt * 8 + lc;
            float v0 = acc[mt][nt][0], v1 = acc[mt][nt][1];
            float v2 = acc[mt][nt][2], v3 = acc[mt][nt][3];
            if (j.bias) {
                float b0v = __ldg(j.bias + gcol), b1v = __ldg(j.bias + gcol + 1);
                v0 += b0v; v1 += b1v; v2 += b0v; v3 += b1v;
            }
            if (j.rowTab) {
                v0 += __ldg(j.rowTab + (size_t)lab0 * j.ldTab + gcol);
                v1 += __ldg(j.rowTab + (size_t)lab0 * j.ldTab + gcol + 1);
                v2 += __ldg(j.rowTab + (size_t)lab1 * j.ldTab + gcol);
                v3 += __ldg(j.rowTab + (size_t)lab1 * j.ldTab + gcol + 1);
            }
            if (j.relu) {
                v0 = fmaxf(v0, 0.f); v1 = fmaxf(v1, 0.f);
                v2 = fmaxf(v2, 0.f); v3 = fmaxf(v3, 0.f);
            }
            if (j.outF) {
                *(float2*)(j.outF + (size_t)grow * j.ldo + gcol)       = make_float2(v0, v1);
                *(float2*)(j.outF + (size_t)(grow + 8) * j.ldo + gcol) = make_float2(v2, v3);
            }
            if (j.outH) {
                __nv_bfloat16 h0, l0, h1, l1, h2, l2, h3, l3;
                split2(v0, h0, l0); split2(v1, h1, l1);
                split2(v2, h2, l2); split2(v3, h3, l3);
                *(__nv_bfloat162*)(j.outH + (size_t)grow * j.ldo + gcol)       = __nv_bfloat162(h0, h1);
                *(__nv_bfloat162*)(j.outL + (size_t)grow * j.ldo + gcol)       = __nv_bfloat162(l0, l1);
                *(__nv_bfloat162*)(j.outH + (size_t)(grow + 8) * j.ldo + gcol) = __nv_bfloat162(h2, h3);
                *(__nv_bfloat162*)(j.outL + (size_t)(grow + 8) * j.ldo + gcol) = __nv_bfloat162(l2, l3);
            }
        }
    }
}

// ---------------- per-entity linear terms ----------------
__global__ void lin_kernel(const float* __restrict__ lW) {
    int m = blockIdx.x;
    int warp = threadIdx.x >> 5;
    int lane = threadIdx.x & 31;
    const float* src = (warp == 0) ? (g_eH + (size_t)m * HH2) : (g_eT + (size_t)m * HH2);
    int wbase = warp * HH2;
    float a0 = 0.f, a1 = 0.f;
    for (int i = lane; i < HH2; i += 32) {
        float x = src[i];
        a0 = fmaf(x, lW[(wbase + i) * 2 + 0], a0);
        a1 = fmaf(x, lW[(wbase + i) * 2 + 1], a1);
    }
#pragma unroll
    for (int off = 16; off; off >>= 1) {
        a0 += __shfl_xor_sync(0xffffffffu, a0, off);
        a1 += __shfl_xor_sync(0xffffffffu, a1, off);
    }
    if (lane == 0) {
        float* dst = (warp == 0) ? g_hlin : g_tlin;
        dst[m * 2 + 0] = a0;
        dst[m * 2 + 1] = a1;
    }
}

// ---------------- per-relation logits + NLL partials ----------------
__global__ void rel_kernel(const int* __restrict__ rel_head, const int* __restrict__ rel_tail,
                           const int* __restrict__ rel_label, const float* __restrict__ lb,
                           float* __restrict__ out_logits) {
    int warp = threadIdx.x >> 5;
    int lane = threadIdx.x & 31;
    int r = blockIdx.x * 8 + warp;
    int b = r / RR;
    int hidx = rel_head[r];
    int tidx = rel_tail[r];
    size_t hm = (size_t)(b * EE + hidx);
    size_t tm = (size_t)(b * EE + tidx);
    const float* hbrow = g_hb + hm * (2 * HH2);
    const float* trow  = g_eT + tm * HH2;
    float a0 = 0.f, a1 = 0.f;
    for (int jx = lane; jx < HH2; jx += 32) {
        float t = trow[jx];
        a0 = fmaf(hbrow[jx],       t, a0);
        a1 = fmaf(hbrow[HH2 + jx], t, a1);
    }
#pragma unroll
    for (int off = 16; off; off >>= 1) {
        a0 += __shfl_xor_sync(0xffffffffu, a0, off);
        a1 += __shfl_xor_sync(0xffffffffu, a1, off);
    }
    __shared__ float sloss[8];
    if (lane == 0) {
        float l0 = a0 + g_hlin[hm * 2 + 0] + g_tlin[tm * 2 + 0] + lb[0];
        float l1 = a1 + g_hlin[hm * 2 + 1] + g_tlin[tm * 2 + 1] + lb[1];
        out_logits[(size_t)r * 2 + 0] = l0;
        out_logits[(size_t)r * 2 + 1] = l1;
        float mx = fmaxf(l0, l1);
        float lse = mx + logf(expf(l0 - mx) + expf(l1 - mx));
        int lab = rel_label[r];
        sloss[warp] = (lab ? l1 : l0) - lse;
    }
    __syncthreads();
    if (threadIdx.x == 0) {
        float s = 0.f;
#pragma unroll
        for (int i = 0; i < 8; i++) s += sloss[i];
        g_partials[blockIdx.x] = s;
    }
}

__global__ void loss_reduce_kernel(float* __restrict__ out_loss) {
    __shared__ float sh[256];
    float s = 0.f;
    for (int i = threadIdx.x; i < RELBLOCKS; i += 256) s += g_partials[i];
    sh[threadIdx.x] = s;
    __syncthreads();
    for (int off = 128; off; off >>= 1) {
        if (threadIdx.x < off) sh[threadIdx.x] += sh[threadIdx.x + off];
        __syncthreads();
    }
    if (threadIdx.x == 0) *out_loss = -sh[0] / (float)NREL;
}

// ---------------- host launch ----------------
#define SMEM128 (2 * (2 * 128 * 80 + 20480))   // 81920
#define SMEM64  (2 * (2 * 64 * 80 + 20480))    // 61440

extern "C" void kernel_launch(void* const* d_in, const int* in_sizes, int n_in,
                              void* d_out, int out_size) {
    const float* hs        = (const float*)d_in[0];
    const float* emb       = (const float*)d_in[1];
    const float* hW1       = (const float*)d_in[2];
    const float* hb1       = (const float*)d_in[3];
    const float* hW2       = (const float*)d_in[4];
    const float* hb2       = (const float*)d_in[5];
    const float* tW1       = (const float*)d_in[6];
    const float* tb1       = (const float*)d_in[7];
    const float* tW2       = (const float*)d_in[8];
    const float* tb2       = (const float*)d_in[9];
    const float* bil_w     = (const float*)d_in[10];
    const float* lW        = (const float*)d_in[11];
    const float* lb        = (const float*)d_in[12];
    const int*   ent_start = (const int*)d_in[13];
    const int*   ent_label = (const int*)d_in[14];
    const int*   rel_head  = (const int*)d_in[15];
    const int*   rel_tail  = (const int*)d_in[16];
    const int*   rel_label = (const int*)d_in[17];

    cudaFuncSetAttribute(mma_gemm<128>, cudaFuncAttributeMaxDynamicSharedMemorySize, SMEM128);
    cudaFuncSetAttribute(mma_gemm<64>,  cudaFuncAttributeMaxDynamicSharedMemorySize, SMEM64);

    __nv_bfloat16 *p_repH, *p_repL, *p_w1H, *p_w1L, *p_h1H, *p_h1L;
    __nv_bfloat16 *p_w2hH, *p_w2hL, *p_w2tH, *p_w2tL, *p_eHH, *p_eHL, *p_bilH, *p_bilL;
    float *p_eH, *p_eT, *p_hb, *p_embW1;
    cudaGetSymbolAddress((void**)&p_repH, g_repH); cudaGetSymbolAddress((void**)&p_repL, g_repL);
    cudaGetSymbolAddress((void**)&p_w1H,  g_w1H ); cudaGetSymbolAddress((void**)&p_w1L,  g_w1L );
    cudaGetSymbolAddress((void**)&p_h1H,  g_h1H ); cudaGetSymbolAddress((void**)&p_h1L,  g_h1L );
    cudaGetSymbolAddress((void**)&p_w2hH, g_w2hH); cudaGetSymbolAddress((void**)&p_w2hL, g_w2hL);
    cudaGetSymbolAddress((void**)&p_w2tH, g_w2tH); cudaGetSymbolAddress((void**)&p_w2tL, g_w2tL);
    cudaGetSymbolAddress((void**)&p_eHH,  g_eHH ); cudaGetSymbolAddress((void**)&p_eHL,  g_eHL );
    cudaGetSymbolAddress((void**)&p_bilH, g_bilH); cudaGetSymbolAddress((void**)&p_bilL, g_bilL);
    cudaGetSymbolAddress((void**)&p_eH,   g_eH  ); cudaGetSymbolAddress((void**)&p_eT,   g_eT  );
    cudaGetSymbolAddress((void**)&p_hb,   g_hb  ); cudaGetSymbolAddress((void**)&p_embW1, g_embW1);

    const int logit_elems = NREL * 2;
    int off = out_size - logit_elems;
    if (off < 0) off = 0;
    float* logits_out = (float*)d_out + off;

    // 1) independent prep: gather hid, emb@W1_bot table, all weight converts
    gather_kernel<<<ME, 256>>>(hs, ent_start);
    embw1_kernel<<<576, 256>>>(emb, hW1, hb1, tW1, tb1);
    wconv_all<<<2016, dim3(32, 8)>>>(hW1, tW1, hW2, tW2, bil_w);

    // 2) layer 1 (fused head|tail): [2048,768] x [1536,768]^T + embW1[label], relu, bf16 out
    {
        GJob j = {};
        j.aH = p_repH; j.aL = p_repL; j.lda = DD;
        j.bH = p_w1H;  j.bL = p_w1L;
        j.rowTab = p_embW1; j.rowLab = ent_label; j.ldTab = N1;
        j.outH = p_h1H; j.outL = p_h1L; j.ldo = N1;
        j.relu = 1;
        mma_gemm<128><<<dim3(N1 / 128, ME / 128), 256, SMEM128>>>(j, j, 999, DD);
    }
    // 3) layer 2 merged (head tower + tail tower), BM=64, grid (6,32)=192 CTAs
    {
        GJob jh = {}, jt = {};
        jh.aH = p_h1H;      jh.aL = p_h1L;      jh.lda = N1;
        jh.bH = p_w2hH;     jh.bL = p_w2hL;
        jh.bias = hb2;
        jh.outH = p_eHH; jh.outL = p_eHL; jh.outF = p_eH; jh.ldo = HH2;
        jh.relu = 1;
        jt.aH = p_h1H + HH; jt.aL = p_h1L + HH; jt.lda = N1;
        jt.bH = p_w2tH;     jt.bL = p_w2tL;
        jt.bias = tb2;
        jt.outF = p_eT; jt.ldo = HH2;
        jt.relu = 1;
        mma_gemm<64><<<dim3(6, ME / 64), 256, SMEM64>>>(jh, jt, 3, HH);
    }
    // 4) bilinear precompute: hb[m, o*384+j] = sum_i eH[m,i] * bil_w[o,i,j], BM=64, 192 CTAs
    {
        GJob j = {};
        j.aH = p_eHH; j.aL = p_eHL; j.lda = HH2;
        j.bH = p_bilH; j.bL = p_bilL;
        j.outF = p_hb; j.ldo = 2 * HH2;
        j.relu = 0;
        mma_gemm<64><<<dim3(2 * HH2 / 128, ME / 64), 256, SMEM64>>>(j, j, 999, HH2);
    }

    // 5) per-entity linear terms
    lin_kernel<<<ME, 64>>>(lW);

    // 6) per-relation logits + loss partials
    rel_kernel<<<RELBLOCKS, 256>>>(rel_head, rel_tail, rel_label, lb, logits_out);

    // 7) loss
    if (off >= 1) loss_reduce_kernel<<<1, 256>>>((float*)d_out);
}

// round 8
// speedup vs baseline: 2.8382x; 1.0592x over previous
#include <cuda_runtime.h>
#include <cuda_bf16.h>
#include <stdint.h>
#include <math.h>

// ---------------- problem constants ----------------
#define BB   16
#define SS_  512
#define DD   768
#define EE   128
#define RR   2048
#define HH   768
#define HH2  384
#define ME   (BB * EE)        // 2048 entity rows
#define NREL (BB * RR)        // 32768 relations
#define RELBLOCKS (NREL / 8)
#define N1   (2 * HH)         // 1536 (head|tail fused layer1 output)

// ---------------- scratch (static device globals) ----------------
__device__ __nv_bfloat16 g_repH[ME * DD],  g_repL[ME * DD];
__device__ __nv_bfloat16 g_w1H [N1 * DD],  g_w1L [N1 * DD];
__device__ __nv_bfloat16 g_h1H [ME * N1],  g_h1L [ME * N1];
__device__ __nv_bfloat16 g_w2hH[HH2 * HH], g_w2hL[HH2 * HH];
__device__ __nv_bfloat16 g_w2tH[HH2 * HH], g_w2tL[HH2 * HH];
__device__ __nv_bfloat16 g_eHH [ME * HH2], g_eHL [ME * HH2];
__device__ __nv_bfloat16 g_bilH[2 * HH2 * HH2], g_bilL[2 * HH2 * HH2];
__device__ float g_embW1[3 * N1];
__device__ float g_eH[ME * HH2], g_eT[ME * HH2];
__device__ float g_hb[ME * 2 * HH2];
__device__ float g_hlin[ME * 2], g_tlin[ME * 2];
__device__ float g_partials[RELBLOCKS];

// ---------------- helpers ----------------
__device__ __forceinline__ uint32_t smem_u32(const void* p) {
    uint32_t a;
    asm("{ .reg .u64 t; cvta.to.shared.u64 t, %1; cvt.u32.u64 %0, t; }" : "=r"(a) : "l"(p));
    return a;
}
__device__ __forceinline__ void cpa16(uint32_t dst, const void* src) {
    asm volatile("cp.async.cg.shared.global [%0], [%1], 16;" :: "r"(dst), "l"(src));
}
#define CP_COMMIT() asm volatile("cp.async.commit_group;" ::: "memory")

#define LDSM4(r, addr) \
    asm volatile("ldmatrix.sync.aligned.m8n8.x4.shared.b16 {%0,%1,%2,%3}, [%4];" \
        : "=r"((r)[0]), "=r"((r)[1]), "=r"((r)[2]), "=r"((r)[3]) : "r"(addr))

#define MMA16816(d, a, b) \
    asm volatile("mma.sync.aligned.m16n8k16.row.col.f32.bf16.bf16.f32 " \
        "{%0,%1,%2,%3}, {%4,%5,%6,%7}, {%8,%9}, {%0,%1,%2,%3};" \
        : "+f"((d)[0]), "+f"((d)[1]), "+f"((d)[2]), "+f"((d)[3]) \
        : "r"((a)[0]), "r"((a)[1]), "r"((a)[2]), "r"((a)[3]), "r"((b)[0]), "r"((b)[1]))

__device__ __forceinline__ void split2(float x, __nv_bfloat16& h, __nv_bfloat16& l) {
    h = __float2bfloat16(x);
    l = __float2bfloat16(x - __bfloat162float(h));
}

// ---------------- gather + convert (hid part only) ----------------
__global__ void gather_kernel(const float* __restrict__ hs,
                              const int* __restrict__ es) {
    int m = blockIdx.x;
    int b = m >> 7;
    int s = es[m];
    const float* src = hs + ((size_t)b * SS_ + s) * DD;
    size_t rb = (size_t)m * DD;
    for (int i = threadIdx.x; i < DD; i += 256) {
        __nv_bfloat16 h, l;
        split2(src[i], h, l);
        g_repH[rb + i] = h; g_repL[rb + i] = l;
    }
}

// ---------------- embW1[l, n] = emb[l] @ W1_bottom[:, n] + b1[n]  (exact fp32) ----------------
__global__ void embw1_kernel(const float* __restrict__ emb,
                             const float* __restrict__ hW1, const float* __restrict__ hb1,
                             const float* __restrict__ tW1, const float* __restrict__ tb1) {
    int o = blockIdx.x * 8 + (threadIdx.x >> 5);
    int lane = threadIdx.x & 31;
    int l = o / N1, n = o % N1;
    const float* er = emb + (size_t)l * DD;
    const float* w;
    float bias;
    if (n < HH) { w = hW1 + (size_t)DD * HH + n;        bias = hb1[n]; }
    else        { w = tW1 + (size_t)DD * HH + (n - HH); bias = tb1[n - HH]; }
    float a = 0.f;
    for (int k = lane; k < DD; k += 32) a = fmaf(er[k], w[(size_t)k * HH], a);
#pragma unroll
    for (int off = 16; off; off >>= 1) a += __shfl_xor_sync(0xffffffffu, a, off);
    if (lane == 0) g_embW1[o] = a + bias;
}

// ---------------- all weight transposes+converts in ONE launch ----------------
__global__ void wconv_all(const float* __restrict__ hW1, const float* __restrict__ tW1,
                          const float* __restrict__ hW2, const float* __restrict__ tW2,
                          const float* __restrict__ bil) {
    __shared__ float t[32][33];
    int id = blockIdx.x;
    const float* W; int K, N; __nv_bfloat16 *oH, *oL;
    if (id < 576)       { W = hW1;             K = 768; N = 768; oH = g_w1H;             oL = g_w1L; }
    else if (id < 1152) { W = tW1;             K = 768; N = 768; oH = g_w1H + 768 * 768; oL = g_w1L + 768 * 768; id -= 576; }
    else if (id < 1440) { W = hW2;             K = 768; N = 384; oH = g_w2hH;            oL = g_w2hL; id -= 1152; }
    else if (id < 1728) { W = tW2;             K = 768; N = 384; oH = g_w2tH;            oL = g_w2tL; id -= 1440; }
    else if (id < 1872) { W = bil;             K = 384; N = 384; oH = g_bilH;            oL = g_bilL; id -= 1728; }
    else                { W = bil + 384 * 384; K = 384; N = 384; oH = g_bilH + 384 * 384; oL = g_bilL + 384 * 384; id -= 1872; }
    int ntiles = N / 32;
    int n0 = (id % ntiles) * 32, k0 = (id / ntiles) * 32;
    int tx = threadIdx.x, ty = threadIdx.y;
#pragma unroll
    for (int j = 0; j < 32; j += 8)
        t[ty + j][tx] = W[(size_t)(k0 + ty + j) * N + n0 + tx];
    __syncthreads();
#pragma unroll
    for (int j = 0; j < 32; j += 8) {
        int n = n0 + ty + j, k = k0 + tx;
        __nv_bfloat16 h, l;
        split2(t[tx][ty + j], h, l);
        oH[(size_t)n * K + k] = h;
        oL[(size_t)n * K + k] = l;
    }
}

// ---------------- mma.sync split-bf16 GEMM, multi-stage cp.async pipeline ----------------
struct GJob {
    const __nv_bfloat16 *aH, *aL; int lda;
    const __nv_bfloat16 *bH, *bL;            // ldb = K
    const float* bias;
    const float* rowTab; const int* rowLab; int ldTab;
    __nv_bfloat16 *outH, *outL;
    float* outF;
    int ldo;
    int relu;
};

template <int BM>
__device__ __forceinline__ void load_stage(uint32_t sbase, const GJob& j,
                                           int m0, int n0, int k0, int tid, int K) {
    const int ACH = BM * 4;                  // 16B chunks per A matrix
#pragma unroll
    for (int idx = tid; idx < 2 * ACH + 1024; idx += 256) {
        if (idx < ACH) {
            int row = idx >> 2, ch = idx & 3;
            cpa16(sbase + row * 80 + ch * 16, j.aH + (size_t)(m0 + row) * j.lda + k0 + ch * 8);
        } else if (idx < 2 * ACH) {
            int q = idx - ACH; int row = q >> 2, ch = q & 3;
            cpa16(sbase + BM * 80 + row * 80 + ch * 16, j.aL + (size_t)(m0 + row) * j.lda + k0 + ch * 8);
        } else if (idx < 2 * ACH + 512) {
            int q = idx - 2 * ACH; int row = q >> 2, ch = q & 3;
            cpa16(sbase + 2 * BM * 80 + row * 80 + ch * 16, j.bH + (size_t)(n0 + row) * K + k0 + ch * 8);
        } else {
            int q = idx - 2 * ACH - 512; int row = q >> 2, ch = q & 3;
            cpa16(sbase + 2 * BM * 80 + 10240 + row * 80 + ch * 16, j.bL + (size_t)(n0 + row) * K + k0 + ch * 8);
        }
    }
}

template <int BM, int STAGES, int MINB>
__global__ void __launch_bounds__(256, MINB)
mma_gemm(GJob j0, GJob j1, int splitX, int K) {
    constexpr int MT = BM / 32;
    constexpr int MAT_A = BM * 80;
    constexpr int OFF_B = 2 * BM * 80;
    constexpr int STAGE = 2 * BM * 80 + 20480;
    extern __shared__ char smem[];
    const uint32_t sb = smem_u32(smem);
    const int tid = threadIdx.x;
    const int wid = tid >> 5, lane = tid & 31;

    const int isJ1 = (blockIdx.x >= splitX);
    const GJob j = isJ1 ? j1 : j0;
    const int nx = blockIdx.x - (isJ1 ? splitX : 0);
    const int m0 = blockIdx.y * BM, n0 = nx * 128;
    const int warpM = (wid >> 2) * (BM / 2);
    const int warpN = (wid & 3) * 32;

    const uint32_t aOff = (warpM + (lane & 15)) * 80 + (lane >> 4) * 16;
    const uint32_t bOff = (warpN + (lane & 7) + ((lane >> 4) & 1) * 8) * 80
                        + ((lane >> 3) & 1) * 16;

    float acc[MT][4][4];
#pragma unroll
    for (int i = 0; i < MT; i++)
#pragma unroll
        for (int jt = 0; jt < 4; jt++)
#pragma unroll
            for (int q = 0; q < 4; q++) acc[i][jt][q] = 0.f;

    const int NC = K >> 5;

    // prologue: fill STAGES-1 stages (always commit so group counting is uniform)
#pragma unroll
    for (int s = 0; s < STAGES - 1; s++) {
        if (s < NC) load_stage<BM>(sb + s * STAGE, j, m0, n0, s * 32, tid, K);
        CP_COMMIT();
    }

    for (int c = 0; c < NC; c++) {
        asm volatile("cp.async.wait_group %0;" :: "n"(STAGES - 2) : "memory");
        __syncthreads();

        // prefetch chunk c+STAGES-1 into slot (c-1) mod STAGES (safe: all warps done with it)
        int pf = c + STAGES - 1;
        if (pf < NC) load_stage<BM>(sb + (pf % STAGES) * STAGE, j, m0, n0, pf * 32, tid, K);
        CP_COMMIT();

        const uint32_t st = sb + (c % STAGES) * STAGE;
#pragma unroll
        for (int ks = 0; ks < 2; ks++) {
            uint32_t ah[MT][4], al[MT][4], bh[2][4], bl[2][4];
#pragma unroll
            for (int mt = 0; mt < MT; mt++) {
                uint32_t ad = st + aOff + mt * (16 * 80) + ks * 32;
                LDSM4(ah[mt], ad);
                LDSM4(al[mt], ad + MAT_A);
            }
#pragma unroll
            for (int np = 0; np < 2; np++) {
                uint32_t bd = st + OFF_B + bOff + np * (16 * 80) + ks * 32;
                LDSM4(bh[np], bd);
                LDSM4(bl[np], bd + 10240);
            }
#pragma unroll
            for (int mt = 0; mt < MT; mt++)
#pragma unroll
                for (int nt = 0; nt < 4; nt++) {
                    uint32_t* bhp = &bh[nt >> 1][(nt & 1) * 2];
                    uint32_t* blp = &bl[nt >> 1][(nt & 1) * 2];
                    MMA16816(acc[mt][nt], ah[mt], bhp);
                    MMA16816(acc[mt][nt], ah[mt], blp);
                    MMA16816(acc[mt][nt], al[mt], bhp);
                }
        }
    }

    // ---------------- epilogue ----------------
    const int lr = lane >> 2;
    const int lc = (lane & 3) * 2;
#pragma unroll
    for (int mt = 0; mt < MT; mt++) {
        int grow = m0 + warpM + mt * 16 + lr;
        int lab0 = 0, lab1 = 0;
        if (j.rowTab) { lab0 = j.rowLab[grow]; lab1 = j.rowLab[grow + 8]; }
#pragma unroll
        for (int nt = 0; nt < 4; nt++) {
            int gcol = n0 + warpN + nt * 8 + lc;
            float v0 = acc[mt][nt][0], v1 = acc[mt][nt][1];
            float v2 = acc[mt][nt][2], v3 = acc[mt][nt][3];
            if (j.bias) {
                float b0v = __ldg(j.bias + gcol), b1v = __ldg(j.bias + gcol + 1);
                v0 += b0v; v1 += b1v; v2 += b0v; v3 += b1v;
            }
            if (j.rowTab) {
                v0 += __ldg(j.rowTab + (size_t)lab0 * j.ldTab + gcol);
                v1 += __ldg(j.rowTab + (size_t)lab0 * j.ldTab + gcol + 1);
                v2 += __ldg(j.rowTab + (size_t)lab1 * j.ldTab + gcol);
                v3 += __ldg(j.rowTab + (size_t)lab1 * j.ldTab + gcol + 1);
            }
            if (j.relu) {
                v0 = fmaxf(v0, 0.f); v1 = fmaxf(v1, 0.f);
                v2 = fmaxf(v2, 0.f); v3 = fmaxf(v3, 0.f);
            }
            if (j.outF) {
                *(float2*)(j.outF + (size_t)grow * j.ldo + gcol)       = make_float2(v0, v1);
                *(float2*)(j.outF + (size_t)(grow + 8) * j.ldo + gcol) = make_float2(v2, v3);
            }
            if (j.outH) {
                __nv_bfloat16 h0, l0, h1, l1, h2, l2, h3, l3;
                split2(v0, h0, l0); split2(v1, h1, l1);
                split2(v2, h2, l2); split2(v3, h3, l3);
                *(__nv_bfloat162*)(j.outH + (size_t)grow * j.ldo + gcol)       = __nv_bfloat162(h0, h1);
                *(__nv_bfloat162*)(j.outL + (size_t)grow * j.ldo + gcol)       = __nv_bfloat162(l0, l1);
                *(__nv_bfloat162*)(j.outH + (size_t)(grow + 8) * j.ldo + gcol) = __nv_bfloat162(h2, h3);
                *(__nv_bfloat162*)(j.outL + (size_t)(grow + 8) * j.ldo + gcol) = __nv_bfloat162(l2, l3);
            }
        }
    }
}

// ---------------- per-entity linear terms ----------------
__global__ void lin_kernel(const float* __restrict__ lW) {
    int m = blockIdx.x;
    int warp = threadIdx.x >> 5;
    int lane = threadIdx.x & 31;
    const float* src = (warp == 0) ? (g_eH + (size_t)m * HH2) : (g_eT + (size_t)m * HH2);
    int wbase = warp * HH2;
    float a0 = 0.f, a1 = 0.f;
    for (int i = lane; i < HH2; i += 32) {
        float x = src[i];
        a0 = fmaf(x, lW[(wbase + i) * 2 + 0], a0);
        a1 = fmaf(x, lW[(wbase + i) * 2 + 1], a1);
    }
#pragma unroll
    for (int off = 16; off; off >>= 1) {
        a0 += __shfl_xor_sync(0xffffffffu, a0, off);
        a1 += __shfl_xor_sync(0xffffffffu, a1, off);
    }
    if (lane == 0) {
        float* dst = (warp == 0) ? g_hlin : g_tlin;
        dst[m * 2 + 0] = a0;
        dst[m * 2 + 1] = a1;
    }
}

// ---------------- per-relation logits + NLL partials (float4-vectorized) ----------------
__global__ void rel_kernel(const int* __restrict__ rel_head, const int* __restrict__ rel_tail,
                           const int* __restrict__ rel_label, const float* __restrict__ lb,
                           float* __restrict__ out_logits) {
    int warp = threadIdx.x >> 5;
    int lane = threadIdx.x & 31;
    int r = blockIdx.x * 8 + warp;
    int b = r / RR;
    int hidx = rel_head[r];
    int tidx = rel_tail[r];
    size_t hm = (size_t)(b * EE + hidx);
    size_t tm = (size_t)(b * EE + tidx);
    const float4* hb4 = (const float4*)(g_hb + hm * (2 * HH2));   // 192 float4: [o0 x96 | o1 x96]
    const float4* t4  = (const float4*)(g_eT + tm * HH2);         // 96 float4
    float a0 = 0.f, a1 = 0.f;
#pragma unroll
    for (int i = 0; i < 3; i++) {
        int jx = i * 32 + lane;
        float4 t = t4[jx];
        float4 h0 = hb4[jx];
        float4 h1 = hb4[96 + jx];
        a0 = fmaf(h0.x, t.x, a0); a0 = fmaf(h0.y, t.y, a0);
        a0 = fmaf(h0.z, t.z, a0); a0 = fmaf(h0.w, t.w, a0);
        a1 = fmaf(h1.x, t.x, a1); a1 = fmaf(h1.y, t.y, a1);
        a1 = fmaf(h1.z, t.z, a1); a1 = fmaf(h1.w, t.w, a1);
    }
#pragma unroll
    for (int off = 16; off; off >>= 1) {
        a0 += __shfl_xor_sync(0xffffffffu, a0, off);
        a1 += __shfl_xor_sync(0xffffffffu, a1, off);
    }
    __shared__ float sloss[8];
    if (lane == 0) {
        float l0 = a0 + g_hlin[hm * 2 + 0] + g_tlin[tm * 2 + 0] + lb[0];
        float l1 = a1 + g_hlin[hm * 2 + 1] + g_tlin[tm * 2 + 1] + lb[1];
        out_logits[(size_t)r * 2 + 0] = l0;
        out_logits[(size_t)r * 2 + 1] = l1;
        float mx = fmaxf(l0, l1);
        float lse = mx + logf(expf(l0 - mx) + expf(l1 - mx));
        int lab = rel_label[r];
        sloss[warp] = (lab ? l1 : l0) - lse;
    }
    __syncthreads();
    if (threadIdx.x == 0) {
        float s = 0.f;
#pragma unroll
        for (int i = 0; i < 8; i++) s += sloss[i];
        g_partials[blockIdx.x] = s;
    }
}

__global__ void loss_reduce_kernel(float* __restrict__ out_loss) {
    __shared__ float sh[256];
    float s = 0.f;
    for (int i = threadIdx.x; i < RELBLOCKS; i += 256) s += g_partials[i];
    sh[threadIdx.x] = s;
    __syncthreads();
    for (int off = 128; off; off >>= 1) {
        if (threadIdx.x < off) sh[threadIdx.x] += sh[threadIdx.x + off];
        __syncthreads();
    }
    if (threadIdx.x == 0) *out_loss = -sh[0] / (float)NREL;
}

// ---------------- host launch ----------------
#define SMEM128 (4 * (2 * 128 * 80 + 20480))   // 163840, 4 stages, 1 CTA/SM
#define SMEM64  (3 * (2 * 64 * 80 + 20480))    // 92160, 3 stages, 2 CTA/SM

extern "C" void kernel_launch(void* const* d_in, const int* in_sizes, int n_in,
                              void* d_out, int out_size) {
    const float* hs        = (const float*)d_in[0];
    const float* emb       = (const float*)d_in[1];
    const float* hW1       = (const float*)d_in[2];
    const float* hb1       = (const float*)d_in[3];
    const float* hW2       = (const float*)d_in[4];
    const float* hb2       = (const float*)d_in[5];
    const float* tW1       = (const float*)d_in[6];
    const float* tb1       = (const float*)d_in[7];
    const float* tW2       = (const float*)d_in[8];
    const float* tb2       = (const float*)d_in[9];
    const float* bil_w     = (const float*)d_in[10];
    const float* lW        = (const float*)d_in[11];
    const float* lb        = (const float*)d_in[12];
    const int*   ent_start = (const int*)d_in[13];
    const int*   ent_label = (const int*)d_in[14];
    const int*   rel_head  = (const int*)d_in[15];
    const int*   rel_tail  = (const int*)d_in[16];
    const int*   rel_label = (const int*)d_in[17];

    cudaFuncSetAttribute(mma_gemm<128, 4, 1>, cudaFuncAttributeMaxDynamicSharedMemorySize, SMEM128);
    cudaFuncSetAttribute(mma_gemm<64,  3, 2>, cudaFuncAttributeMaxDynamicSharedMemorySize, SMEM64);

    __nv_bfloat16 *p_repH, *p_repL, *p_w1H, *p_w1L, *p_h1H, *p_h1L;
    __nv_bfloat16 *p_w2hH, *p_w2hL, *p_w2tH, *p_w2tL, *p_eHH, *p_eHL, *p_bilH, *p_bilL;
    float *p_eH, *p_eT, *p_hb, *p_embW1;
    cudaGetSymbolAddress((void**)&p_repH, g_repH); cudaGetSymbolAddress((void**)&p_repL, g_repL);
    cudaGetSymbolAddress((void**)&p_w1H,  g_w1H ); cudaGetSymbolAddress((void**)&p_w1L,  g_w1L );
    cudaGetSymbolAddress((void**)&p_h1H,  g_h1H ); cudaGetSymbolAddress((void**)&p_h1L,  g_h1L );
    cudaGetSymbolAddress((void**)&p_w2hH, g_w2hH); cudaGetSymbolAddress((void**)&p_w2hL, g_w2hL);
    cudaGetSymbolAddress((void**)&p_w2tH, g_w2tH); cudaGetSymbolAddress((void**)&p_w2tL, g_w2tL);
    cudaGetSymbolAddress((void**)&p_eHH,  g_eHH ); cudaGetSymbolAddress((void**)&p_eHL,  g_eHL );
    cudaGetSymbolAddress((void**)&p_bilH, g_bilH); cudaGetSymbolAddress((void**)&p_bilL, g_bilL);
    cudaGetSymbolAddress((void**)&p_eH,   g_eH  ); cudaGetSymbolAddress((void**)&p_eT,   g_eT  );
    cudaGetSymbolAddress((void**)&p_hb,   g_hb  ); cudaGetSymbolAddress((void**)&p_embW1, g_embW1);

    const int logit_elems = NREL * 2;
    int off = out_size - logit_elems;
    if (off < 0) off = 0;
    float* logits_out = (float*)d_out + off;

    // 1) independent prep
    gather_kernel<<<ME, 256>>>(hs, ent_start);
    embw1_kernel<<<576, 256>>>(emb, hW1, hb1, tW1, tb1);
    wconv_all<<<2016, dim3(32, 8)>>>(hW1, tW1, hW2, tW2, bil_w);

    // 2) layer 1 (fused head|tail): [2048,768] x [1536,768]^T + embW1[label], relu
    {
        GJob j = {};
        j.aH = p_repH; j.aL = p_repL; j.lda = DD;
        j.bH = p_w1H;  j.bL = p_w1L;
        j.rowTab = p_embW1; j.rowLab = ent_label; j.ldTab = N1;
        j.outH = p_h1H; j.outL = p_h1L; j.ldo = N1;
        j.relu = 1;
        mma_gemm<128, 4, 1><<<dim3(N1 / 128, ME / 128), 256, SMEM128>>>(j, j, 999, DD);
    }
    // 3) layer 2 merged (head + tail towers), BM=64, 192 CTAs, 2 CTA/SM
    {
        GJob jh = {}, jt = {};
        jh.aH = p_h1H;      jh.aL = p_h1L;      jh.lda = N1;
        jh.bH = p_w2hH;     jh.bL = p_w2hL;
        jh.bias = hb2;
        jh.outH = p_eHH; jh.outL = p_eHL; jh.outF = p_eH; jh.ldo = HH2;
        jh.relu = 1;
        jt.aH = p_h1H + HH; jt.aL = p_h1L + HH; jt.lda = N1;
        jt.bH = p_w2tH;     jt.bL = p_w2tL;
        jt.bias = tb2;
        jt.outF = p_eT; jt.ldo = HH2;
        jt.relu = 1;
        mma_gemm<64, 3, 2><<<dim3(6, ME / 64), 256, SMEM64>>>(jh, jt, 3, HH);
    }
    // 4) bilinear precompute, BM=64, 192 CTAs, 2 CTA/SM
    {
        GJob j = {};
        j.aH = p_eHH; j.aL = p_eHL; j.lda = HH2;
        j.bH = p_bilH; j.bL = p_bilL;
        j.outF = p_hb; j.ldo = 2 * HH2;
        j.relu = 0;
        mma_gemm<64, 3, 2><<<dim3(2 * HH2 / 128, ME / 64), 256, SMEM64>>>(j, j, 999, HH2);
    }

    // 5) per-entity linear terms
    lin_kernel<<<ME, 64>>>(lW);

    // 6) per-relation logits + loss partials
    rel_kernel<<<RELBLOCKS, 256>>>(rel_head, rel_tail, rel_label, lb, logits_out);

    // 7) loss
    if (off >= 1) loss_reduce_kernel<<<1, 256>>>((float*)d_out);
}